// round 9
// baseline (speedup 1.0000x reference)
#include <cuda_runtime.h>
#include <cuda_fp16.h>
#include <math.h>
#include <stdint.h>

// Problem constants (fixed: S=1024, B=16, I=D=1024, L=2)
#define S_LEN 1024
#define BATCH 16
#define DIM   1024
#define GDIM  (4 * DIM)       // 4096
#define KDIM  1024
#define MROWS (S_LEN * BATCH) // 16384
#define EPS 1e-6f

// ---------------------------------------------------------------------------
// Device scratch (no allocation allowed in kernel_launch)
// ---------------------------------------------------------------------------
__device__ __half g_pre[(size_t)S_LEN * BATCH * GDIM];  // 134 MB (NO bias; fp16)
__device__ __half g_ah[(size_t)MROWS * KDIM];           // 33.5 MB (A in fp16)
__device__ __half g_wh0[(size_t)GDIM * KDIM];           // 8.4 MB  (W0 fp16)
__device__ __half g_wh1[(size_t)GDIM * KDIM];           // 8.4 MB  (W1 fp16)

// ---------------------------------------------------------------------------
// PTX helpers — base-target only (NO tcgen05: harness emits compute_103 PTX)
// ---------------------------------------------------------------------------
__device__ __forceinline__ uint32_t smem_u32(const void* p) {
    uint32_t a;
    asm("{ .reg .u64 t; cvta.to.shared.u64 t, %1; cvt.u32.u64 %0, t; }"
        : "=r"(a) : "l"(p));
    return a;
}
__device__ __forceinline__ void cp16(uint32_t dst, const void* src) {
    asm volatile("cp.async.cg.shared.global [%0], [%1], 16;"
                 :: "r"(dst), "l"(src));
}
__device__ __forceinline__ void ldsm_x4(uint32_t& r0, uint32_t& r1,
                                        uint32_t& r2, uint32_t& r3,
                                        uint32_t addr) {
    asm volatile("ldmatrix.sync.aligned.m8n8.x4.shared.b16 {%0,%1,%2,%3}, [%4];"
                 : "=r"(r0), "=r"(r1), "=r"(r2), "=r"(r3) : "r"(addr));
}
__device__ __forceinline__ void mma_f16(float* d, const uint32_t* a,
                                        uint32_t b0, uint32_t b1) {
    asm volatile(
        "mma.sync.aligned.m16n8k16.row.col.f32.f16.f16.f32 "
        "{%0,%1,%2,%3}, {%4,%5,%6,%7}, {%8,%9}, {%0,%1,%2,%3};"
        : "+f"(d[0]), "+f"(d[1]), "+f"(d[2]), "+f"(d[3])
        : "r"(a[0]), "r"(a[1]), "r"(a[2]), "r"(a[3]), "r"(b0), "r"(b1));
}

// Fast math (rel err ~2^-21; far under the 1e-3 budget)
__device__ __forceinline__ float fast_sigmoid(float x) {
    return __fdividef(1.0f, 1.0f + __expf(-x));
}
__device__ __forceinline__ float fast_tanh(float x) {
    float e = __expf(2.0f * x);
    return __fdividef(e - 1.0f, e + 1.0f);
}

// Swizzle: rows are 64B (32 fp16); XOR the 16B-segment index with (row>>1)&3
__device__ __forceinline__ uint32_t swz_addr(uint32_t plane_base, int row, int seg) {
    return plane_base + (uint32_t)(row * 64) + ((uint32_t)((seg ^ ((row >> 1) & 3)) << 4));
}

// ---------------------------------------------------------------------------
// fp32 -> fp16 convert kernel. n multiple of 4.
// ---------------------------------------------------------------------------
__global__ __launch_bounds__(256)
void convert_kernel(const float* __restrict__ src,
                    __half* __restrict__ dst, int n)
{
    int i = (blockIdx.x * 256 + threadIdx.x) * 4;
    if (i >= n) return;
    float4 v = *reinterpret_cast<const float4*>(src + i);
    __half2* d2 = reinterpret_cast<__half2*>(dst + i);
    d2[0] = __half2(__float2half(v.x), __float2half(v.y));
    d2[1] = __half2(__float2half(v.z), __float2half(v.w));
}

// ---------------------------------------------------------------------------
// HMMA GEMM: C[M=16384, N=4096] = A[M,K=1024] @ W[N,K]^T   (fp16 in/out,
// fp32 accum, NO bias — scan adds it in fp32).
// CTA tile 128x256, 8 warps in 2(M) x 4(N), warp tile 64x64 (high
// MMA:LDSM ratio — GEMM is L1/shared-bound per ncu R8).
// K-chunk 32, 4-stage cp.async pipeline (24KB/stage), 1 CTA/SM.
// ---------------------------------------------------------------------------
#define BM 128
#define BN 256
#define KCHUNK 32
#define NCHUNK (KDIM / KCHUNK)       // 32
#define PLANE_A (BM * 64)            // 8 KB
#define PLANE_W (BN * 64)            // 16 KB
#define STAGE_BYTES (PLANE_A + PLANE_W)    // 24 KB
#define STAGES 4
#define GEMM_SMEM (STAGES * STAGE_BYTES)   // 96 KB

__device__ __forceinline__ void load_chunk(uint32_t stage_base,
                                           const __half* Ap,
                                           const __half* Wp,
                                           int k0, int tid)
{
    // A: 128 rows x 4 segs = 512 cp16 ; W: 256 rows x 4 segs = 1024 cp16
#pragma unroll
    for (int h = 0; h < 2; h++) {
        int it = tid + h * 256;          // 0..511
        int row = it >> 2;
        int seg = it & 3;
        cp16(swz_addr(stage_base, row, seg),
             Ap + (size_t)row * KDIM + k0 + seg * 8);
    }
#pragma unroll
    for (int h = 0; h < 4; h++) {
        int it = tid + h * 256;          // 0..1023
        int row = it >> 2;
        int seg = it & 3;
        cp16(swz_addr(stage_base + PLANE_A, row, seg),
             Wp + (size_t)row * KDIM + k0 + seg * 8);
    }
}

__global__ __launch_bounds__(256, 1)
void gemm_tc_kernel(const __half* __restrict__ Ah,
                    const __half* __restrict__ Wh,
                    __half* __restrict__ C)
{
    extern __shared__ __align__(1024) char smem[];
    const uint32_t sbase = smem_u32(smem);
    const int tid  = threadIdx.x;
    const int wid  = tid >> 5;
    const int lane = tid & 31;
    const int warp_m = wid & 1;     // 2 warps in M: 64 rows each
    const int warp_n = wid >> 1;    // 4 warps in N: 64 cols each
    const int bm = blockIdx.y * BM;
    const int bn = blockIdx.x * BN;

    const __half* Ap = Ah + (size_t)bm * KDIM;
    const __half* Wp = Wh + (size_t)bn * KDIM;

    float acc[4][8][4];
#pragma unroll
    for (int i = 0; i < 4; i++)
#pragma unroll
        for (int j = 0; j < 8; j++)
#pragma unroll
            for (int k = 0; k < 4; k++) acc[i][j][k] = 0.0f;

    // Prologue: stages 0,1,2
    load_chunk(sbase + 0 * STAGE_BYTES, Ap, Wp, 0 * KCHUNK, tid);
    asm volatile("cp.async.commit_group;");
    load_chunk(sbase + 1 * STAGE_BYTES, Ap, Wp, 1 * KCHUNK, tid);
    asm volatile("cp.async.commit_group;");
    load_chunk(sbase + 2 * STAGE_BYTES, Ap, Wp, 2 * KCHUNK, tid);
    asm volatile("cp.async.commit_group;");

    const int a_lrow = lane & 15;
    const int a_lseg = lane >> 4;
    const int b_lrow = (lane & 7) + ((lane >> 4) << 3);
    const int b_lseg = (lane >> 3) & 1;

    for (int i = 0; i < NCHUNK; i++) {
        const int rem = NCHUNK - 1 - i;
        if (rem >= 2)      { asm volatile("cp.async.wait_group 2;"); }
        else if (rem == 1) { asm volatile("cp.async.wait_group 1;"); }
        else               { asm volatile("cp.async.wait_group 0;"); }
        __syncthreads();

        if (i + 3 < NCHUNK) {
            load_chunk(sbase + (uint32_t)((i + 3) % STAGES) * STAGE_BYTES,
                       Ap, Wp, (i + 3) * KCHUNK, tid);
            asm volatile("cp.async.commit_group;");
        }

        const uint32_t st = sbase + (uint32_t)(i % STAGES) * STAGE_BYTES;
        const uint32_t base_a = st;
        const uint32_t base_w = st + PLANE_A;

#pragma unroll
        for (int ks = 0; ks < 2; ks++) {
            uint32_t a[4][4], w[4][4];
#pragma unroll
            for (int jj = 0; jj < 4; jj++) {
                int row = warp_n * 64 + jj * 16 + b_lrow;
                ldsm_x4(w[jj][0], w[jj][1], w[jj][2], w[jj][3],
                        swz_addr(base_w, row, ks * 2 + b_lseg));
            }
#pragma unroll
            for (int ti = 0; ti < 4; ti++) {
                int row = warp_m * 64 + ti * 16 + a_lrow;
                ldsm_x4(a[ti][0], a[ti][1], a[ti][2], a[ti][3],
                        swz_addr(base_a, row, ks * 2 + a_lseg));
            }
#pragma unroll
            for (int ti = 0; ti < 4; ti++)
#pragma unroll
                for (int jj = 0; jj < 4; jj++) {
                    mma_f16(acc[ti][2 * jj + 0], a[ti], w[jj][0], w[jj][1]);
                    mma_f16(acc[ti][2 * jj + 1], a[ti], w[jj][2], w[jj][3]);
                }
        }
    }

    // Epilogue: fp16 streaming stores (C read once by the scan; 134MB)
    const int mrow0 = bm + warp_m * 64 + (lane >> 2);
    const int col0  = bn + warp_n * 64 + (lane & 3) * 2;
#pragma unroll
    for (int ti = 0; ti < 4; ti++) {
        const int r0 = mrow0 + ti * 16;
#pragma unroll
        for (int g = 0; g < 8; g++) {
            int col = col0 + g * 8;
            __half2 v0 = __floats2half2_rn(acc[ti][g][0], acc[ti][g][1]);
            __half2 v1 = __floats2half2_rn(acc[ti][g][2], acc[ti][g][3]);
            __stcs(reinterpret_cast<__half2*>(C + (size_t)r0 * GDIM + col), v0);
            __stcs(reinterpret_cast<__half2*>(C + (size_t)(r0 + 8) * GDIM + col), v1);
        }
    }
}

// ---------------------------------------------------------------------------
// Elementwise sLSTM scan: fp16 pre (bias-free) staged via cp.async, triple
// buffered (3 x 16-step tiles = 24 KB). Bias added in fp32 here.
// EMIT_HALF: layer-0 writes h as fp16 (feeds GEMM1 A directly).
// ---------------------------------------------------------------------------
#define CH 16
#define NCH (S_LEN / CH)   // 64 chunks

template <bool EMIT_HALF>
__global__ __launch_bounds__(64)
void slstm_scan_kernel(const __half* __restrict__ pre,    // [S,B,4D] (no bias)
                       const float* __restrict__ bias,    // [4D]
                       const float* __restrict__ r,       // [4D]
                       const float* __restrict__ h0,      // [L,B,D]
                       const float* __restrict__ extra0,  // [L,B,3D]
                       int layer,
                       float* __restrict__ out_f32,       // [S,B,D] (or null)
                       __half* __restrict__ out_h16,      // [S,B,D] (or null)
                       float* __restrict__ hf,            // [L,B,D]
                       float* __restrict__ extraf)        // [L,B,3D]
{
    __shared__ __half buf[3][CH][4][64];   // 24 KB

    const int ltid = threadIdx.x;                 // 0..63
    const int L0 = blockIdx.x * 64;               // lane base (all same b)
    const int b  = L0 >> 10;
    const int d0 = L0 & (DIM - 1);
    const int d  = d0 + ltid;

    const float rz = r[0 * DIM + d];
    const float ri = r[1 * DIM + d];
    const float rf = r[2 * DIM + d];
    const float ro = r[3 * DIM + d];
    const float bz = bias[0 * DIM + d];
    const float bi = bias[1 * DIM + d];
    const float bf = bias[2 * DIM + d];
    const float bo = bias[3 * DIM + d];
    const bool rzero = (rz == 0.0f) && (ri == 0.0f) && (rf == 0.0f) && (ro == 0.0f);

    const size_t lbd  = (size_t)layer * BATCH * DIM + (size_t)b * DIM;
    const size_t lb3d = (size_t)layer * BATCH * 3 * DIM + (size_t)b * 3 * DIM;

    float h = h0[lbd + d];
    float c = extra0[lb3d + 0 * DIM + d];
    float n = extra0[lb3d + 1 * DIM + d];
    float m = extra0[lb3d + 2 * DIM + d];

    // Prefetch mapping: g = gate (0..3), cc = 16B chunk (0..7: lanes cc*8..+7),
    // sh = step parity. Each thread issues CH/2 cp16 per chunk.
    const int g  = ltid >> 4;
    const int cc = ltid & 7;
    const int sh = (ltid >> 3) & 1;
    const size_t strideT = (size_t)BATCH * GDIM;
    const __half* src0 = pre + (size_t)b * GDIM + (size_t)g * DIM + d0 + cc * 8;

#define SCAN_PREFETCH(stage, k)                                               \
    do {                                                                      \
        const __half* _s = src0 + ((size_t)(k) * CH + sh) * strideT;          \
        _Pragma("unroll")                                                     \
        for (int _jj = 0; _jj < CH / 2; _jj++) {                              \
            cp16(smem_u32(&buf[stage][2 * _jj + sh][g][cc * 8]), _s);         \
            _s += 2 * strideT;                                                \
        }                                                                     \
        asm volatile("cp.async.commit_group;");                               \
    } while (0)

    SCAN_PREFETCH(0, 0);
    SCAN_PREFETCH(1, 1);
    SCAN_PREFETCH(2, 2);

    size_t outIdx = (size_t)b * DIM + d;
    const size_t strideO = (size_t)BATCH * DIM;

    for (int k = 0; k < NCH; k++) {
        if (k + 2 < NCH)      { asm volatile("cp.async.wait_group 2;"); }
        else if (k + 1 < NCH) { asm volatile("cp.async.wait_group 1;"); }
        else                  { asm volatile("cp.async.wait_group 0;"); }
        __syncthreads();

        const int cur = k % 3;

        if (rzero) {
            float zt[CH], ot[CH];
#pragma unroll
            for (int j = 0; j < CH; j++) {
                zt[j] = fast_tanh(__half2float(buf[cur][j][0][ltid]) + bz);
                ot[j] = fast_sigmoid(__half2float(buf[cur][j][3][ltid]) + bo);
            }
#pragma unroll
            for (int j = 0; j < CH; j++) {
                const float ip = __half2float(buf[cur][j][1][ltid]) + bi;
                const float fm = __half2float(buf[cur][j][2][ltid]) + bf + m;
                const float mn = fmaxf(fm, ip);
                const float ft = __expf(fm - mn);
                const float it = __expf(ip - mn);
                c = ft * c + it * zt[j];
                n = ft * n + it;
                m = mn;
                h = ot[j] * __fdividef(c, fabsf(n) + EPS);
                if (EMIT_HALF) out_h16[outIdx] = __float2half(h);
                else           __stcs(out_f32 + outIdx, h);
                outIdx += strideO;
            }
        } else {
#pragma unroll
            for (int j = 0; j < CH; j++) {
                const float zp = __half2float(buf[cur][j][0][ltid]) + bz + rz * h;
                const float ip = __half2float(buf[cur][j][1][ltid]) + bi + ri * h;
                const float fp = __half2float(buf[cur][j][2][ltid]) + bf + rf * h;
                const float op = __half2float(buf[cur][j][3][ltid]) + bo + ro * h;
                const float zt = fast_tanh(zp);
                const float ot = fast_sigmoid(op);
                const float fm = fp + m;
                const float mn = fmaxf(fm, ip);
                const float ft = __expf(fm - mn);
                const float it = __expf(ip - mn);
                c = ft * c + it * zt;
                n = ft * n + it;
                m = mn;
                h = ot * __fdividef(c, fabsf(n) + EPS);
                if (EMIT_HALF) out_h16[outIdx] = __float2half(h);
                else           __stcs(out_f32 + outIdx, h);
                outIdx += strideO;
            }
        }
        __syncthreads();   // all reads of buf[cur] done before refill

        if (k + 3 < NCH) {
            SCAN_PREFETCH(cur, k + 3);
        }
    }
#undef SCAN_PREFETCH

    hf[lbd + d] = h;
    extraf[lb3d + 0 * DIM + d] = c;
    extraf[lb3d + 1 * DIM + d] = n;
    extraf[lb3d + 2 * DIM + d] = m;
}

// ---------------------------------------------------------------------------
// Launch. Inputs: input, h0, extra0, W0, b0, r0, W1, b1, r1
// Output: output[S,B,D] || h_f[L,B,D] || extra_f[L,B,3D]
// ---------------------------------------------------------------------------
extern "C" void kernel_launch(void* const* d_in, const int* in_sizes, int n_in,
                              void* d_out, int out_size)
{
    const float* input  = (const float*)d_in[0];
    const float* h0     = (const float*)d_in[1];
    const float* extra0 = (const float*)d_in[2];
    const float* W0     = (const float*)d_in[3];
    const float* b0     = (const float*)d_in[4];
    const float* r0     = (const float*)d_in[5];
    const float* W1     = (const float*)d_in[6];
    const float* b1     = (const float*)d_in[7];
    const float* r1     = (const float*)d_in[8];

    float* out    = (float*)d_out;
    float* hf     = out + (size_t)S_LEN * BATCH * DIM;
    float* extraf = hf + (size_t)2 * BATCH * DIM;

    __half* pre;  cudaGetSymbolAddress((void**)&pre, g_pre);
    __half* ah;   cudaGetSymbolAddress((void**)&ah,  g_ah);
    __half* wh0;  cudaGetSymbolAddress((void**)&wh0, g_wh0);
    __half* wh1;  cudaGetSymbolAddress((void**)&wh1, g_wh1);

    cudaFuncSetAttribute(gemm_tc_kernel,
                         cudaFuncAttributeMaxDynamicSharedMemorySize, GEMM_SMEM);

    const int nA = MROWS * KDIM;   // 16.7M
    const int nW = GDIM * KDIM;    // 4.2M

    dim3 gemmGrid(GDIM / BN, MROWS / BM);     // (16, 128)
    dim3 scanGrid((BATCH * DIM) / 64);        // 256

    // All converts up front (wh1 is independent of layer-0's pipeline)
    convert_kernel<<<nA / 1024, 256>>>(input, ah, nA);
    convert_kernel<<<nW / 1024, 256>>>(W0, wh0, nW);
    convert_kernel<<<nW / 1024, 256>>>(W1, wh1, nW);

    // ---- Layer 0 ----
    gemm_tc_kernel<<<gemmGrid, 256, GEMM_SMEM>>>(ah, wh0, pre);
    slstm_scan_kernel<true><<<scanGrid, 64>>>(pre, b0, r0, h0, extra0, 0,
                                              nullptr, ah, hf, extraf);

    // ---- Layer 1 ----
    gemm_tc_kernel<<<gemmGrid, 256, GEMM_SMEM>>>(ah, wh1, pre);
    slstm_scan_kernel<false><<<scanGrid, 64>>>(pre, b1, r1, h0, extra0, 1,
                                               out, nullptr, hf, extraf);
}

// round 10
// speedup vs baseline: 1.1344x; 1.1344x over previous
#include <cuda_runtime.h>
#include <cuda_fp16.h>
#include <math.h>
#include <stdint.h>

// Problem constants (fixed: S=1024, B=16, I=D=1024, L=2)
#define S_LEN 1024
#define BATCH 16
#define DIM   1024
#define GDIM  (4 * DIM)       // 4096
#define KDIM  1024
#define MROWS (S_LEN * BATCH) // 16384
#define EPS 1e-6f

// ---------------------------------------------------------------------------
// Device scratch (no allocation allowed in kernel_launch)
// ---------------------------------------------------------------------------
__device__ __half g_pre[(size_t)S_LEN * BATCH * GDIM];  // 134 MB (NO bias; fp16)
__device__ __half g_ah[(size_t)MROWS * KDIM];           // 33.5 MB (A in fp16)
__device__ __half g_wh0[(size_t)GDIM * KDIM];           // 8.4 MB  (W0 fp16)
__device__ __half g_wh1[(size_t)GDIM * KDIM];           // 8.4 MB  (W1 fp16)

// ---------------------------------------------------------------------------
// PTX helpers — base-target only (NO tcgen05: harness emits compute_103 PTX)
// ---------------------------------------------------------------------------
__device__ __forceinline__ uint32_t smem_u32(const void* p) {
    uint32_t a;
    asm("{ .reg .u64 t; cvta.to.shared.u64 t, %1; cvt.u32.u64 %0, t; }"
        : "=r"(a) : "l"(p));
    return a;
}
__device__ __forceinline__ void cp16(uint32_t dst, const void* src) {
    asm volatile("cp.async.cg.shared.global [%0], [%1], 16;"
                 :: "r"(dst), "l"(src));
}
__device__ __forceinline__ void ldsm_x4(uint32_t& r0, uint32_t& r1,
                                        uint32_t& r2, uint32_t& r3,
                                        uint32_t addr) {
    asm volatile("ldmatrix.sync.aligned.m8n8.x4.shared.b16 {%0,%1,%2,%3}, [%4];"
                 : "=r"(r0), "=r"(r1), "=r"(r2), "=r"(r3) : "r"(addr));
}
__device__ __forceinline__ void mma_f16(float* d, const uint32_t* a,
                                        uint32_t b0, uint32_t b1) {
    asm volatile(
        "mma.sync.aligned.m16n8k16.row.col.f32.f16.f16.f32 "
        "{%0,%1,%2,%3}, {%4,%5,%6,%7}, {%8,%9}, {%0,%1,%2,%3};"
        : "+f"(d[0]), "+f"(d[1]), "+f"(d[2]), "+f"(d[3])
        : "r"(a[0]), "r"(a[1]), "r"(a[2]), "r"(a[3]), "r"(b0), "r"(b1));
}

// Fast math (rel err ~2^-21; far under the 1e-3 budget)
__device__ __forceinline__ float fast_sigmoid(float x) {
    return __fdividef(1.0f, 1.0f + __expf(-x));
}
__device__ __forceinline__ float fast_tanh(float x) {
    float e = __expf(2.0f * x);
    return __fdividef(e - 1.0f, e + 1.0f);
}

// Swizzle: rows are 64B (32 fp16); XOR the 16B-segment index with (row>>1)&3
__device__ __forceinline__ uint32_t swz_addr(uint32_t plane_base, int row, int seg) {
    return plane_base + (uint32_t)(row * 64) + ((uint32_t)((seg ^ ((row >> 1) & 3)) << 4));
}

// ---------------------------------------------------------------------------
// fp32 -> fp16 convert kernel. n multiple of 4.
// ---------------------------------------------------------------------------
__global__ __launch_bounds__(256)
void convert_kernel(const float* __restrict__ src,
                    __half* __restrict__ dst, int n)
{
    int i = (blockIdx.x * 256 + threadIdx.x) * 4;
    if (i >= n) return;
    float4 v = *reinterpret_cast<const float4*>(src + i);
    __half2* d2 = reinterpret_cast<__half2*>(dst + i);
    d2[0] = __half2(__float2half(v.x), __float2half(v.y));
    d2[1] = __half2(__float2half(v.z), __float2half(v.w));
}

// ---------------------------------------------------------------------------
// HMMA GEMM: C[M=16384, N=4096] = A[M,K=1024] @ W[N,K]^T   (fp16 in/out,
// fp32 accum, NO bias — scan adds it in fp32).
// R8 shape: CTA 128x128, 8 warps (4M x 2N, 32x64 warp tile), K-chunk 64,
// 3-stage cp.async pipeline (32KB/stage), 2 CTAs/SM.
// NEW (R10): ksub-level fragment double-buffering — load the next k16's
// ldsm fragments before issuing the current k16's MMAs, hiding LDS latency
// inside each warp instead of relying on cross-warp overlap.
// ---------------------------------------------------------------------------
#define KCHUNK 64
#define NCHUNK (KDIM / KCHUNK)       // 16
#define PLANE  8192                  // 128 rows * 64 bytes (one 32-k sub-plane)
#define SUB_BYTES (2 * PLANE)        // [A, W] for one 32-k sub-chunk
#define STAGE_BYTES (2 * SUB_BYTES)  // 32 KB
#define STAGES 3
#define GEMM_SMEM (STAGES * STAGE_BYTES)   // 96 KB

__device__ __forceinline__ void load_chunk(uint32_t stage_base,
                                           const __half* Ap,
                                           const __half* Wp,
                                           int k0, int tid)
{
#pragma unroll
    for (int sub = 0; sub < 2; sub++) {
#pragma unroll
        for (int p = 0; p < 2; p++) {
            const __half* src = (p == 0) ? Ap : Wp;
#pragma unroll
            for (int h = 0; h < 2; h++) {
                int it = tid + h * 256;          // 0..511
                int row = it >> 2;
                int seg = it & 3;
                cp16(swz_addr(stage_base + sub * SUB_BYTES + p * PLANE, row, seg),
                     src + (size_t)row * KDIM + k0 + sub * 32 + seg * 8);
            }
        }
    }
}

__global__ __launch_bounds__(256, 2)
void gemm_tc_kernel(const __half* __restrict__ Ah,
                    const __half* __restrict__ Wh,
                    __half* __restrict__ C)
{
    extern __shared__ __align__(1024) char smem[];
    const uint32_t sbase = smem_u32(smem);
    const int tid  = threadIdx.x;
    const int wid  = tid >> 5;
    const int lane = tid & 31;
    const int warp_m = wid & 3;     // 4 warps in M: 32 rows each
    const int warp_n = wid >> 2;    // 2 warps in N: 64 cols each
    const int bm = blockIdx.y * 128;
    const int bn = blockIdx.x * 128;

    const __half* Ap = Ah + (size_t)bm * KDIM;
    const __half* Wp = Wh + (size_t)bn * KDIM;

    float acc[2][8][4];
#pragma unroll
    for (int i = 0; i < 2; i++)
#pragma unroll
        for (int j = 0; j < 8; j++)
#pragma unroll
            for (int k = 0; k < 4; k++) acc[i][j][k] = 0.0f;

    load_chunk(sbase + 0 * STAGE_BYTES, Ap, Wp, 0 * KCHUNK, tid);
    asm volatile("cp.async.commit_group;");
    load_chunk(sbase + 1 * STAGE_BYTES, Ap, Wp, 1 * KCHUNK, tid);
    asm volatile("cp.async.commit_group;");

    const int a_lrow = lane & 15;
    const int a_lseg = lane >> 4;
    const int b_lrow = (lane & 7) + ((lane >> 4) << 3);
    const int b_lseg = (lane >> 3) & 1;

    // Double-buffered fragments (2 buffers x [A 2x4 + W 4x4] = 48 regs)
    uint32_t a[2][2][4], w[2][4][4];

#define LOAD_FRAGS(buf, st, ksub)                                             \
    do {                                                                      \
        const int _sub = (ksub) >> 1;                                         \
        const int _ks  = (ksub) & 1;                                          \
        const uint32_t _ba = (st) + _sub * SUB_BYTES;                         \
        const uint32_t _bw = _ba + PLANE;                                     \
        _Pragma("unroll")                                                     \
        for (int _jj = 0; _jj < 4; _jj++) {                                   \
            int _row = warp_n * 64 + _jj * 16 + b_lrow;                       \
            ldsm_x4(w[buf][_jj][0], w[buf][_jj][1],                           \
                    w[buf][_jj][2], w[buf][_jj][3],                           \
                    swz_addr(_bw, _row, _ks * 2 + b_lseg));                   \
        }                                                                     \
        _Pragma("unroll")                                                     \
        for (int _ti = 0; _ti < 2; _ti++) {                                   \
            int _row = warp_m * 32 + _ti * 16 + a_lrow;                       \
            ldsm_x4(a[buf][_ti][0], a[buf][_ti][1],                           \
                    a[buf][_ti][2], a[buf][_ti][3],                           \
                    swz_addr(_ba, _row, _ks * 2 + a_lseg));                   \
        }                                                                     \
    } while (0)

    for (int i = 0; i < NCHUNK; i++) {
        if (i + 1 < NCHUNK) { asm volatile("cp.async.wait_group 1;"); }
        else                { asm volatile("cp.async.wait_group 0;"); }
        __syncthreads();

        const uint32_t st = sbase + (uint32_t)(i % STAGES) * STAGE_BYTES;

        // Start consuming immediately, then kick off the next chunk's fill.
        LOAD_FRAGS(0, st, 0);

        if (i + 2 < NCHUNK) {
            load_chunk(sbase + (uint32_t)((i + 2) % STAGES) * STAGE_BYTES,
                       Ap, Wp, (i + 2) * KCHUNK, tid);
            asm volatile("cp.async.commit_group;");
        }

#pragma unroll
        for (int ksub = 0; ksub < 4; ksub++) {
            const int cur = ksub & 1;
            if (ksub < 3) {
                LOAD_FRAGS(cur ^ 1, st, ksub + 1);   // prefetch next k16
            }
#pragma unroll
            for (int ti = 0; ti < 2; ti++)
#pragma unroll
                for (int jj = 0; jj < 4; jj++) {
                    mma_f16(acc[ti][2 * jj + 0], a[cur][ti],
                            w[cur][jj][0], w[cur][jj][1]);
                    mma_f16(acc[ti][2 * jj + 1], a[cur][ti],
                            w[cur][jj][2], w[cur][jj][3]);
                }
        }
    }
#undef LOAD_FRAGS

    // Epilogue: fp16 streaming stores (C read once by the scan; 134MB)
    const int mrow0 = bm + warp_m * 32 + (lane >> 2);
    const int col0  = bn + warp_n * 64 + (lane & 3) * 2;
#pragma unroll
    for (int ti = 0; ti < 2; ti++) {
#pragma unroll
        for (int g = 0; g < 8; g++) {
            int col = col0 + g * 8;
            int r0 = mrow0 + ti * 16;
            __half2 v0 = __floats2half2_rn(acc[ti][g][0], acc[ti][g][1]);
            __half2 v1 = __floats2half2_rn(acc[ti][g][2], acc[ti][g][3]);
            __stcs(reinterpret_cast<__half2*>(C + (size_t)r0 * GDIM + col), v0);
            __stcs(reinterpret_cast<__half2*>(C + (size_t)(r0 + 8) * GDIM + col), v1);
        }
    }
}

// ---------------------------------------------------------------------------
// Elementwise sLSTM scan: fp16 pre (bias-free) staged via cp.async, triple
// buffered (3 x 16-step tiles = 24 KB). Bias added in fp32 here.
// EMIT_HALF: layer-0 writes h as fp16 (feeds GEMM1 A directly).
// ---------------------------------------------------------------------------
#define CH 16
#define NCH (S_LEN / CH)   // 64 chunks

template <bool EMIT_HALF>
__global__ __launch_bounds__(64)
void slstm_scan_kernel(const __half* __restrict__ pre,    // [S,B,4D] (no bias)
                       const float* __restrict__ bias,    // [4D]
                       const float* __restrict__ r,       // [4D]
                       const float* __restrict__ h0,      // [L,B,D]
                       const float* __restrict__ extra0,  // [L,B,3D]
                       int layer,
                       float* __restrict__ out_f32,       // [S,B,D] (or null)
                       __half* __restrict__ out_h16,      // [S,B,D] (or null)
                       float* __restrict__ hf,            // [L,B,D]
                       float* __restrict__ extraf)        // [L,B,3D]
{
    __shared__ __half buf[3][CH][4][64];   // 24 KB

    const int ltid = threadIdx.x;                 // 0..63
    const int L0 = blockIdx.x * 64;               // lane base (all same b)
    const int b  = L0 >> 10;
    const int d0 = L0 & (DIM - 1);
    const int d  = d0 + ltid;

    const float rz = r[0 * DIM + d];
    const float ri = r[1 * DIM + d];
    const float rf = r[2 * DIM + d];
    const float ro = r[3 * DIM + d];
    const float bz = bias[0 * DIM + d];
    const float bi = bias[1 * DIM + d];
    const float bf = bias[2 * DIM + d];
    const float bo = bias[3 * DIM + d];
    const bool rzero = (rz == 0.0f) && (ri == 0.0f) && (rf == 0.0f) && (ro == 0.0f);

    const size_t lbd  = (size_t)layer * BATCH * DIM + (size_t)b * DIM;
    const size_t lb3d = (size_t)layer * BATCH * 3 * DIM + (size_t)b * 3 * DIM;

    float h = h0[lbd + d];
    float c = extra0[lb3d + 0 * DIM + d];
    float n = extra0[lb3d + 1 * DIM + d];
    float m = extra0[lb3d + 2 * DIM + d];

    // Prefetch mapping: g = gate (0..3), cc = 16B chunk (0..7: lanes cc*8..+7),
    // sh = step parity. Each thread issues CH/2 cp16 per chunk.
    const int g  = ltid >> 4;
    const int cc = ltid & 7;
    const int sh = (ltid >> 3) & 1;
    const size_t strideT = (size_t)BATCH * GDIM;
    const __half* src0 = pre + (size_t)b * GDIM + (size_t)g * DIM + d0 + cc * 8;

#define SCAN_PREFETCH(stage, k)                                               \
    do {                                                                      \
        const __half* _s = src0 + ((size_t)(k) * CH + sh) * strideT;          \
        _Pragma("unroll")                                                     \
        for (int _jj = 0; _jj < CH / 2; _jj++) {                              \
            cp16(smem_u32(&buf[stage][2 * _jj + sh][g][cc * 8]), _s);         \
            _s += 2 * strideT;                                                \
        }                                                                     \
        asm volatile("cp.async.commit_group;");                               \
    } while (0)

    SCAN_PREFETCH(0, 0);
    SCAN_PREFETCH(1, 1);
    SCAN_PREFETCH(2, 2);

    size_t outIdx = (size_t)b * DIM + d;
    const size_t strideO = (size_t)BATCH * DIM;

    for (int k = 0; k < NCH; k++) {
        if (k + 2 < NCH)      { asm volatile("cp.async.wait_group 2;"); }
        else if (k + 1 < NCH) { asm volatile("cp.async.wait_group 1;"); }
        else                  { asm volatile("cp.async.wait_group 0;"); }
        __syncthreads();

        const int cur = k % 3;

        if (rzero) {
            float zt[CH], ot[CH];
#pragma unroll
            for (int j = 0; j < CH; j++) {
                zt[j] = fast_tanh(__half2float(buf[cur][j][0][ltid]) + bz);
                ot[j] = fast_sigmoid(__half2float(buf[cur][j][3][ltid]) + bo);
            }
#pragma unroll
            for (int j = 0; j < CH; j++) {
                const float ip = __half2float(buf[cur][j][1][ltid]) + bi;
                const float fm = __half2float(buf[cur][j][2][ltid]) + bf + m;
                const float mn = fmaxf(fm, ip);
                const float ft = __expf(fm - mn);
                const float it = __expf(ip - mn);
                c = ft * c + it * zt[j];
                n = ft * n + it;
                m = mn;
                h = ot[j] * __fdividef(c, fabsf(n) + EPS);
                if (EMIT_HALF) out_h16[outIdx] = __float2half(h);
                else           __stcs(out_f32 + outIdx, h);
                outIdx += strideO;
            }
        } else {
#pragma unroll
            for (int j = 0; j < CH; j++) {
                const float zp = __half2float(buf[cur][j][0][ltid]) + bz + rz * h;
                const float ip = __half2float(buf[cur][j][1][ltid]) + bi + ri * h;
                const float fp = __half2float(buf[cur][j][2][ltid]) + bf + rf * h;
                const float op = __half2float(buf[cur][j][3][ltid]) + bo + ro * h;
                const float zt = fast_tanh(zp);
                const float ot = fast_sigmoid(op);
                const float fm = fp + m;
                const float mn = fmaxf(fm, ip);
                const float ft = __expf(fm - mn);
                const float it = __expf(ip - mn);
                c = ft * c + it * zt;
                n = ft * n + it;
                m = mn;
                h = ot * __fdividef(c, fabsf(n) + EPS);
                if (EMIT_HALF) out_h16[outIdx] = __float2half(h);
                else           __stcs(out_f32 + outIdx, h);
                outIdx += strideO;
            }
        }
        __syncthreads();   // all reads of buf[cur] done before refill

        if (k + 3 < NCH) {
            SCAN_PREFETCH(cur, k + 3);
        }
    }
#undef SCAN_PREFETCH

    hf[lbd + d] = h;
    extraf[lb3d + 0 * DIM + d] = c;
    extraf[lb3d + 1 * DIM + d] = n;
    extraf[lb3d + 2 * DIM + d] = m;
}

// ---------------------------------------------------------------------------
// Launch. Inputs: input, h0, extra0, W0, b0, r0, W1, b1, r1
// Output: output[S,B,D] || h_f[L,B,D] || extra_f[L,B,3D]
// ---------------------------------------------------------------------------
extern "C" void kernel_launch(void* const* d_in, const int* in_sizes, int n_in,
                              void* d_out, int out_size)
{
    const float* input  = (const float*)d_in[0];
    const float* h0     = (const float*)d_in[1];
    const float* extra0 = (const float*)d_in[2];
    const float* W0     = (const float*)d_in[3];
    const float* b0     = (const float*)d_in[4];
    const float* r0     = (const float*)d_in[5];
    const float* W1     = (const float*)d_in[6];
    const float* b1     = (const float*)d_in[7];
    const float* r1     = (const float*)d_in[8];

    float* out    = (float*)d_out;
    float* hf     = out + (size_t)S_LEN * BATCH * DIM;
    float* extraf = hf + (size_t)2 * BATCH * DIM;

    __half* pre;  cudaGetSymbolAddress((void**)&pre, g_pre);
    __half* ah;   cudaGetSymbolAddress((void**)&ah,  g_ah);
    __half* wh0;  cudaGetSymbolAddress((void**)&wh0, g_wh0);
    __half* wh1;  cudaGetSymbolAddress((void**)&wh1, g_wh1);

    cudaFuncSetAttribute(gemm_tc_kernel,
                         cudaFuncAttributeMaxDynamicSharedMemorySize, GEMM_SMEM);

    const int nA = MROWS * KDIM;   // 16.7M
    const int nW = GDIM * KDIM;    // 4.2M

    dim3 gemmGrid(GDIM / 128, MROWS / 128);   // (32, 128)
    dim3 scanGrid((BATCH * DIM) / 64);        // 256

    // All converts up front (wh1 is independent of layer-0's pipeline)
    convert_kernel<<<nA / 1024, 256>>>(input, ah, nA);
    convert_kernel<<<nW / 1024, 256>>>(W0, wh0, nW);
    convert_kernel<<<nW / 1024, 256>>>(W1, wh1, nW);

    // ---- Layer 0 ----
    gemm_tc_kernel<<<gemmGrid, 256, GEMM_SMEM>>>(ah, wh0, pre);
    slstm_scan_kernel<true><<<scanGrid, 64>>>(pre, b0, r0, h0, extra0, 0,
                                              nullptr, ah, hf, extraf);

    // ---- Layer 1 ----
    gemm_tc_kernel<<<gemmGrid, 256, GEMM_SMEM>>>(ah, wh1, pre);
    slstm_scan_kernel<false><<<scanGrid, 64>>>(pre, b1, r1, h0, extra0, 1,
                                               out, nullptr, hf, extraf);
}

// round 11
// speedup vs baseline: 1.2718x; 1.1211x over previous
#include <cuda_runtime.h>
#include <cuda_fp16.h>
#include <math.h>
#include <stdint.h>

// Problem constants (fixed: S=1024, B=16, I=D=1024, L=2)
#define S_LEN 1024
#define BATCH 16
#define DIM   1024
#define GDIM  (4 * DIM)       // 4096
#define KDIM  1024
#define MROWS (S_LEN * BATCH) // 16384
#define EPS 1e-6f

// ---------------------------------------------------------------------------
// Device scratch (no allocation allowed in kernel_launch)
// ---------------------------------------------------------------------------
__device__ __half g_pre[(size_t)S_LEN * BATCH * GDIM];  // 134 MB (NO bias; fp16)
__device__ __half g_ah[(size_t)MROWS * KDIM];           // 33.5 MB (A in fp16)
__device__ __half g_wh0[(size_t)GDIM * KDIM];           // 8.4 MB  (W0 fp16)
__device__ __half g_wh1[(size_t)GDIM * KDIM];           // 8.4 MB  (W1 fp16)

// ---------------------------------------------------------------------------
// PTX helpers — base-target only (NO tcgen05: harness emits compute_103 PTX)
// ---------------------------------------------------------------------------
__device__ __forceinline__ uint32_t smem_u32(const void* p) {
    uint32_t a;
    asm("{ .reg .u64 t; cvta.to.shared.u64 t, %1; cvt.u32.u64 %0, t; }"
        : "=r"(a) : "l"(p));
    return a;
}
__device__ __forceinline__ void cp16(uint32_t dst, const void* src) {
    asm volatile("cp.async.cg.shared.global [%0], [%1], 16;"
                 :: "r"(dst), "l"(src));
}
__device__ __forceinline__ void ldsm_x4(uint32_t& r0, uint32_t& r1,
                                        uint32_t& r2, uint32_t& r3,
                                        uint32_t addr) {
    asm volatile("ldmatrix.sync.aligned.m8n8.x4.shared.b16 {%0,%1,%2,%3}, [%4];"
                 : "=r"(r0), "=r"(r1), "=r"(r2), "=r"(r3) : "r"(addr));
}
__device__ __forceinline__ void mma_f16(float* d, const uint32_t* a,
                                        uint32_t b0, uint32_t b1) {
    asm volatile(
        "mma.sync.aligned.m16n8k16.row.col.f32.f16.f16.f32 "
        "{%0,%1,%2,%3}, {%4,%5,%6,%7}, {%8,%9}, {%0,%1,%2,%3};"
        : "+f"(d[0]), "+f"(d[1]), "+f"(d[2]), "+f"(d[3])
        : "r"(a[0]), "r"(a[1]), "r"(a[2]), "r"(a[3]), "r"(b0), "r"(b1));
}

// Fast math (rel err ~2^-21; far under the 1e-3 budget)
__device__ __forceinline__ float fast_sigmoid(float x) {
    return __fdividef(1.0f, 1.0f + __expf(-x));
}
__device__ __forceinline__ float fast_tanh(float x) {
    float e = __expf(2.0f * x);
    return __fdividef(e - 1.0f, e + 1.0f);
}

// Swizzle: rows are 64B (32 fp16); XOR the 16B-segment index with (row>>1)&3
__device__ __forceinline__ uint32_t swz_addr(uint32_t plane_base, int row, int seg) {
    return plane_base + (uint32_t)(row * 64) + ((uint32_t)((seg ^ ((row >> 1) & 3)) << 4));
}

// ---------------------------------------------------------------------------
// fp32 -> fp16 convert kernel. n multiple of 4.
// ---------------------------------------------------------------------------
__global__ __launch_bounds__(256)
void convert_kernel(const float* __restrict__ src,
                    __half* __restrict__ dst, int n)
{
    int i = (blockIdx.x * 256 + threadIdx.x) * 4;
    if (i >= n) return;
    float4 v = *reinterpret_cast<const float4*>(src + i);
    __half2* d2 = reinterpret_cast<__half2*>(dst + i);
    d2[0] = __half2(__float2half(v.x), __float2half(v.y));
    d2[1] = __half2(__float2half(v.z), __float2half(v.w));
}

// ---------------------------------------------------------------------------
// HMMA GEMM: C[M=16384, N=4096] = A[M,K=1024] @ W[N,K]^T   (fp16 in/out,
// fp32 accum, NO bias — scan adds it in fp32).
// R11: CTA 128x128 with ONLY 4 warps (2M x 2N grid, 64x64 warp tiles) in
// 128-thread CTAs, 2 CTAs/SM. Same 8 warps/SM as R9 but two independent
// barrier domains; LDS traffic is 2/3 of R8's (A*wn + W*wm with wn=wm=2),
// making the tensor pipe the sole critical resource.
// K-chunk 32, 4-stage cp.async pipeline (16KB/stage, 64KB/CTA).
// ---------------------------------------------------------------------------
#define KCHUNK 32
#define NCHUNK (KDIM / KCHUNK)       // 32
#define PLANE  8192                  // 128 rows * 64 bytes
#define STAGE_BYTES (2 * PLANE)      // [A, W] = 16 KB
#define STAGES 4
#define GEMM_SMEM (STAGES * STAGE_BYTES)   // 64 KB

__device__ __forceinline__ void load_chunk(uint32_t stage_base,
                                           const __half* Ap,
                                           const __half* Wp,
                                           int k0, int tid)
{
    // 2 planes x 128 rows x 4 segs(16B) = 1024 cp16 / 128 threads = 8 each.
#pragma unroll
    for (int p = 0; p < 2; p++) {
        const __half* src = (p == 0) ? Ap : Wp;
#pragma unroll
        for (int h = 0; h < 4; h++) {
            int it = tid + h * 128;          // 0..511
            int row = it >> 2;
            int seg = it & 3;
            cp16(swz_addr(stage_base + p * PLANE, row, seg),
                 src + (size_t)row * KDIM + k0 + seg * 8);
        }
    }
}

__global__ __launch_bounds__(128, 2)
void gemm_tc_kernel(const __half* __restrict__ Ah,
                    const __half* __restrict__ Wh,
                    __half* __restrict__ C)
{
    extern __shared__ __align__(1024) char smem[];
    const uint32_t sbase = smem_u32(smem);
    const int tid  = threadIdx.x;
    const int wid  = tid >> 5;      // 0..3
    const int lane = tid & 31;
    const int warp_m = wid & 1;     // 2 warps in M: 64 rows each
    const int warp_n = wid >> 1;    // 2 warps in N: 64 cols each
    const int bm = blockIdx.y * 128;
    const int bn = blockIdx.x * 128;

    const __half* Ap = Ah + (size_t)bm * KDIM;
    const __half* Wp = Wh + (size_t)bn * KDIM;

    float acc[4][8][4];
#pragma unroll
    for (int i = 0; i < 4; i++)
#pragma unroll
        for (int j = 0; j < 8; j++)
#pragma unroll
            for (int k = 0; k < 4; k++) acc[i][j][k] = 0.0f;

    // Prologue: stages 0,1,2
    load_chunk(sbase + 0 * STAGE_BYTES, Ap, Wp, 0 * KCHUNK, tid);
    asm volatile("cp.async.commit_group;");
    load_chunk(sbase + 1 * STAGE_BYTES, Ap, Wp, 1 * KCHUNK, tid);
    asm volatile("cp.async.commit_group;");
    load_chunk(sbase + 2 * STAGE_BYTES, Ap, Wp, 2 * KCHUNK, tid);
    asm volatile("cp.async.commit_group;");

    const int a_lrow = lane & 15;
    const int a_lseg = lane >> 4;
    const int b_lrow = (lane & 7) + ((lane >> 4) << 3);
    const int b_lseg = (lane >> 3) & 1;

    for (int i = 0; i < NCHUNK; i++) {
        const int rem = NCHUNK - 1 - i;
        if (rem >= 2)      { asm volatile("cp.async.wait_group 2;"); }
        else if (rem == 1) { asm volatile("cp.async.wait_group 1;"); }
        else               { asm volatile("cp.async.wait_group 0;"); }
        __syncthreads();

        if (i + 3 < NCHUNK) {
            load_chunk(sbase + (uint32_t)((i + 3) % STAGES) * STAGE_BYTES,
                       Ap, Wp, (i + 3) * KCHUNK, tid);
            asm volatile("cp.async.commit_group;");
        }

        const uint32_t st = sbase + (uint32_t)(i % STAGES) * STAGE_BYTES;
        const uint32_t base_a = st;
        const uint32_t base_w = st + PLANE;

#pragma unroll
        for (int ks = 0; ks < 2; ks++) {
            uint32_t a[4][4], w[4][4];
#pragma unroll
            for (int jj = 0; jj < 4; jj++) {
                int row = warp_n * 64 + jj * 16 + b_lrow;
                ldsm_x4(w[jj][0], w[jj][1], w[jj][2], w[jj][3],
                        swz_addr(base_w, row, ks * 2 + b_lseg));
            }
#pragma unroll
            for (int ti = 0; ti < 4; ti++) {
                int row = warp_m * 64 + ti * 16 + a_lrow;
                ldsm_x4(a[ti][0], a[ti][1], a[ti][2], a[ti][3],
                        swz_addr(base_a, row, ks * 2 + a_lseg));
            }
#pragma unroll
            for (int ti = 0; ti < 4; ti++)
#pragma unroll
                for (int jj = 0; jj < 4; jj++) {
                    mma_f16(acc[ti][2 * jj + 0], a[ti], w[jj][0], w[jj][1]);
                    mma_f16(acc[ti][2 * jj + 1], a[ti], w[jj][2], w[jj][3]);
                }
        }
    }

    // Epilogue: fp16 streaming stores (C read once by the scan; 134MB)
    const int mrow0 = bm + warp_m * 64 + (lane >> 2);
    const int col0  = bn + warp_n * 64 + (lane & 3) * 2;
#pragma unroll
    for (int ti = 0; ti < 4; ti++) {
        const int r0 = mrow0 + ti * 16;
#pragma unroll
        for (int g = 0; g < 8; g++) {
            int col = col0 + g * 8;
            __half2 v0 = __floats2half2_rn(acc[ti][g][0], acc[ti][g][1]);
            __half2 v1 = __floats2half2_rn(acc[ti][g][2], acc[ti][g][3]);
            __stcs(reinterpret_cast<__half2*>(C + (size_t)r0 * GDIM + col), v0);
            __stcs(reinterpret_cast<__half2*>(C + (size_t)(r0 + 8) * GDIM + col), v1);
        }
    }
}

// ---------------------------------------------------------------------------
// Elementwise sLSTM scan: fp16 pre (bias-free) staged via cp.async, triple
// buffered (3 x 16-step tiles = 24 KB). Bias added in fp32 here.
// EMIT_HALF: layer-0 writes h as fp16 (feeds GEMM1 A directly).
// ---------------------------------------------------------------------------
#define CH 16
#define NCH (S_LEN / CH)   // 64 chunks

template <bool EMIT_HALF>
__global__ __launch_bounds__(64)
void slstm_scan_kernel(const __half* __restrict__ pre,    // [S,B,4D] (no bias)
                       const float* __restrict__ bias,    // [4D]
                       const float* __restrict__ r,       // [4D]
                       const float* __restrict__ h0,      // [L,B,D]
                       const float* __restrict__ extra0,  // [L,B,3D]
                       int layer,
                       float* __restrict__ out_f32,       // [S,B,D] (or null)
                       __half* __restrict__ out_h16,      // [S,B,D] (or null)
                       float* __restrict__ hf,            // [L,B,D]
                       float* __restrict__ extraf)        // [L,B,3D]
{
    __shared__ __half buf[3][CH][4][64];   // 24 KB

    const int ltid = threadIdx.x;                 // 0..63
    const int L0 = blockIdx.x * 64;               // lane base (all same b)
    const int b  = L0 >> 10;
    const int d0 = L0 & (DIM - 1);
    const int d  = d0 + ltid;

    const float rz = r[0 * DIM + d];
    const float ri = r[1 * DIM + d];
    const float rf = r[2 * DIM + d];
    const float ro = r[3 * DIM + d];
    const float bz = bias[0 * DIM + d];
    const float bi = bias[1 * DIM + d];
    const float bf = bias[2 * DIM + d];
    const float bo = bias[3 * DIM + d];
    const bool rzero = (rz == 0.0f) && (ri == 0.0f) && (rf == 0.0f) && (ro == 0.0f);

    const size_t lbd  = (size_t)layer * BATCH * DIM + (size_t)b * DIM;
    const size_t lb3d = (size_t)layer * BATCH * 3 * DIM + (size_t)b * 3 * DIM;

    float h = h0[lbd + d];
    float c = extra0[lb3d + 0 * DIM + d];
    float n = extra0[lb3d + 1 * DIM + d];
    float m = extra0[lb3d + 2 * DIM + d];

    // Prefetch mapping: g = gate (0..3), cc = 16B chunk (0..7: lanes cc*8..+7),
    // sh = step parity. Each thread issues CH/2 cp16 per chunk.
    const int g  = ltid >> 4;
    const int cc = ltid & 7;
    const int sh = (ltid >> 3) & 1;
    const size_t strideT = (size_t)BATCH * GDIM;
    const __half* src0 = pre + (size_t)b * GDIM + (size_t)g * DIM + d0 + cc * 8;

#define SCAN_PREFETCH(stage, k)                                               \
    do {                                                                      \
        const __half* _s = src0 + ((size_t)(k) * CH + sh) * strideT;          \
        _Pragma("unroll")                                                     \
        for (int _jj = 0; _jj < CH / 2; _jj++) {                              \
            cp16(smem_u32(&buf[stage][2 * _jj + sh][g][cc * 8]), _s);         \
            _s += 2 * strideT;                                                \
        }                                                                     \
        asm volatile("cp.async.commit_group;");                               \
    } while (0)

    SCAN_PREFETCH(0, 0);
    SCAN_PREFETCH(1, 1);
    SCAN_PREFETCH(2, 2);

    size_t outIdx = (size_t)b * DIM + d;
    const size_t strideO = (size_t)BATCH * DIM;

    for (int k = 0; k < NCH; k++) {
        if (k + 2 < NCH)      { asm volatile("cp.async.wait_group 2;"); }
        else if (k + 1 < NCH) { asm volatile("cp.async.wait_group 1;"); }
        else                  { asm volatile("cp.async.wait_group 0;"); }
        __syncthreads();

        const int cur = k % 3;

        if (rzero) {
            float zt[CH], ot[CH];
#pragma unroll
            for (int j = 0; j < CH; j++) {
                zt[j] = fast_tanh(__half2float(buf[cur][j][0][ltid]) + bz);
                ot[j] = fast_sigmoid(__half2float(buf[cur][j][3][ltid]) + bo);
            }
#pragma unroll
            for (int j = 0; j < CH; j++) {
                const float ip = __half2float(buf[cur][j][1][ltid]) + bi;
                const float fm = __half2float(buf[cur][j][2][ltid]) + bf + m;
                const float mn = fmaxf(fm, ip);
                const float ft = __expf(fm - mn);
                const float it = __expf(ip - mn);
                c = ft * c + it * zt[j];
                n = ft * n + it;
                m = mn;
                h = ot[j] * __fdividef(c, fabsf(n) + EPS);
                if (EMIT_HALF) out_h16[outIdx] = __float2half(h);
                else           __stcs(out_f32 + outIdx, h);
                outIdx += strideO;
            }
        } else {
#pragma unroll
            for (int j = 0; j < CH; j++) {
                const float zp = __half2float(buf[cur][j][0][ltid]) + bz + rz * h;
                const float ip = __half2float(buf[cur][j][1][ltid]) + bi + ri * h;
                const float fp = __half2float(buf[cur][j][2][ltid]) + bf + rf * h;
                const float op = __half2float(buf[cur][j][3][ltid]) + bo + ro * h;
                const float zt = fast_tanh(zp);
                const float ot = fast_sigmoid(op);
                const float fm = fp + m;
                const float mn = fmaxf(fm, ip);
                const float ft = __expf(fm - mn);
                const float it = __expf(ip - mn);
                c = ft * c + it * zt;
                n = ft * n + it;
                m = mn;
                h = ot * __fdividef(c, fabsf(n) + EPS);
                if (EMIT_HALF) out_h16[outIdx] = __float2half(h);
                else           __stcs(out_f32 + outIdx, h);
                outIdx += strideO;
            }
        }
        __syncthreads();   // all reads of buf[cur] done before refill

        if (k + 3 < NCH) {
            SCAN_PREFETCH(cur, k + 3);
        }
    }
#undef SCAN_PREFETCH

    hf[lbd + d] = h;
    extraf[lb3d + 0 * DIM + d] = c;
    extraf[lb3d + 1 * DIM + d] = n;
    extraf[lb3d + 2 * DIM + d] = m;
}

// ---------------------------------------------------------------------------
// Launch. Inputs: input, h0, extra0, W0, b0, r0, W1, b1, r1
// Output: output[S,B,D] || h_f[L,B,D] || extra_f[L,B,3D]
// ---------------------------------------------------------------------------
extern "C" void kernel_launch(void* const* d_in, const int* in_sizes, int n_in,
                              void* d_out, int out_size)
{
    const float* input  = (const float*)d_in[0];
    const float* h0     = (const float*)d_in[1];
    const float* extra0 = (const float*)d_in[2];
    const float* W0     = (const float*)d_in[3];
    const float* b0     = (const float*)d_in[4];
    const float* r0     = (const float*)d_in[5];
    const float* W1     = (const float*)d_in[6];
    const float* b1     = (const float*)d_in[7];
    const float* r1     = (const float*)d_in[8];

    float* out    = (float*)d_out;
    float* hf     = out + (size_t)S_LEN * BATCH * DIM;
    float* extraf = hf + (size_t)2 * BATCH * DIM;

    __half* pre;  cudaGetSymbolAddress((void**)&pre, g_pre);
    __half* ah;   cudaGetSymbolAddress((void**)&ah,  g_ah);
    __half* wh0;  cudaGetSymbolAddress((void**)&wh0, g_wh0);
    __half* wh1;  cudaGetSymbolAddress((void**)&wh1, g_wh1);

    cudaFuncSetAttribute(gemm_tc_kernel,
                         cudaFuncAttributeMaxDynamicSharedMemorySize, GEMM_SMEM);

    const int nA = MROWS * KDIM;   // 16.7M
    const int nW = GDIM * KDIM;    // 4.2M

    dim3 gemmGrid(GDIM / 128, MROWS / 128);   // (32, 128) = 4096 CTAs
    dim3 scanGrid((BATCH * DIM) / 64);        // 256

    // All converts up front (wh1 is independent of layer-0's pipeline)
    convert_kernel<<<nA / 1024, 256>>>(input, ah, nA);
    convert_kernel<<<nW / 1024, 256>>>(W0, wh0, nW);
    convert_kernel<<<nW / 1024, 256>>>(W1, wh1, nW);

    // ---- Layer 0 ----
    gemm_tc_kernel<<<gemmGrid, 128, GEMM_SMEM>>>(ah, wh0, pre);
    slstm_scan_kernel<true><<<scanGrid, 64>>>(pre, b0, r0, h0, extra0, 0,
                                              nullptr, ah, hf, extraf);

    // ---- Layer 1 ----
    gemm_tc_kernel<<<gemmGrid, 128, GEMM_SMEM>>>(ah, wh1, pre);
    slstm_scan_kernel<false><<<scanGrid, 64>>>(pre, b1, r1, h0, extra0, 1,
                                               out, nullptr, hf, extraf);
}